// round 8
// baseline (speedup 1.0000x reference)
#include <cuda_runtime.h>
#include <cstddef>

// Problem constants (fixed by setup_inputs)
constexpr int D      = 64;
constexpr int N      = 128;
constexpr int NSTEPS = 16;

// ---------------- device scratch (no allocations allowed) ----------------
__device__ __align__(16) float g_R[NSTEPS][D * D];  // [s][i*64+a] = R_{15-s}[a][i]
__device__ __align__(16) float g_X[NSTEPS][N * D];  // x_s, s = 0..15

// KPREP: direct row-wise simulation of BOTH systems in one launch.
//   rows 0..127   : state rows (x0, v0)            -> g_X[t], traj frames
//   rows 128..191 : propagator rows a = row-128,
//                   X0 = dt^2*e_a, V0 = dt*e_a     -> X_k = R_k, stored transposed
__global__ void __launch_bounds__(128) kprep(const float* __restrict__ x0,
                                             const float* __restrict__ v0,
                                             const float* __restrict__ W,
                                             float* __restrict__ out) {
    __shared__ float sX[4][D];
    const int tid = threadIdx.x;
    const int w   = tid >> 5;                  // warp = local row
    const int l   = tid & 31;
    const int row = blockIdx.x * 4 + w;        // 0..191
    const int c0  = 2 * l;
    const float dt = 0.01f;
    const bool is_state = (row < N);
    const int a = row - N;                     // propagator row index (if !is_state)

    // Load this lane's two M columns into registers (fully unrolled).
    float mA[D], mB[D];
    {
        const float4* wa = (const float4*)(W + (size_t)c0 * D);
        const float4* wb = (const float4*)(W + (size_t)(c0 + 1) * D);
#pragma unroll
        for (int q = 0; q < 16; q++) {
            float4 va = wa[q], vb = wb[q];
            const int k = 4 * q;
            mA[k+0] = va.x - ((k+0) == c0     ? 1.0f : 0.0f);
            mA[k+1] = va.y - ((k+1) == c0     ? 1.0f : 0.0f);
            mA[k+2] = va.z - ((k+2) == c0     ? 1.0f : 0.0f);
            mA[k+3] = va.w - ((k+3) == c0     ? 1.0f : 0.0f);
            mB[k+0] = vb.x - ((k+0) == c0 + 1 ? 1.0f : 0.0f);
            mB[k+1] = vb.y - ((k+1) == c0 + 1 ? 1.0f : 0.0f);
            mB[k+2] = vb.z - ((k+2) == c0 + 1 ? 1.0f : 0.0f);
            mB[k+3] = vb.w - ((k+3) == c0 + 1 ? 1.0f : 0.0f);
        }
    }

    float2 xl, vl;
    if (is_state) {
        xl = *(const float2*)(x0 + (size_t)row * D + c0);
        vl = *(const float2*)(v0 + (size_t)row * D + c0);
    } else {
        xl = make_float2(c0 == a ? dt * dt : 0.0f, (c0 + 1) == a ? dt * dt : 0.0f);
        vl = make_float2(c0 == a ? dt      : 0.0f, (c0 + 1) == a ? dt      : 0.0f);
    }

    if (is_state) {
        *(float2*)&g_X[0][row * D + c0] = xl;                 // x_0
        *(float2*)(out + (size_t)row * D + c0) = xl;          // traj frame 0
    } else {
        g_R[15][c0 * D + a]       = xl.x;                     // R_0 transposed
        g_R[15][(c0 + 1) * D + a] = xl.y;
    }

    *(float2*)&sX[w][c0] = xl;
    __syncwarp();

#pragma unroll 1
    for (int t = 1; t <= NSTEPS; t++) {
        float2 y0 = make_float2(0.0f, 0.0f);
        float2 y1 = make_float2(0.0f, 0.0f);
#pragma unroll
        for (int k = 0; k < D; k += 2) {
            float xk0 = sX[w][k], xk1 = sX[w][k + 1];
            y0.x += xk0 * mA[k];     y0.y += xk0 * mB[k];
            y1.x += xk1 * mA[k + 1]; y1.y += xk1 * mB[k + 1];
        }
        float2 y = make_float2(y0.x + y1.x, y0.y + y1.y);
        vl.x += dt * y.x;  vl.y += dt * y.y;
        xl.x += dt * vl.x; xl.y += dt * vl.y;
        __syncwarp();
        *(float2*)&sX[w][c0] = xl;
        __syncwarp();

        if (is_state) {
            if (t < NSTEPS)
                *(float2*)&g_X[t][row * D + c0] = xl;
            if ((t & 3) == 0) {
                float* o = out + (size_t)(t >> 2) * (N * D) + (size_t)row * D + c0;
                *(float2*)o = xl;
            }
        } else if (t < NSTEPS) {
            g_R[15 - t][c0 * D + a]       = xl.x;
            g_R[15 - t][(c0 + 1) * D + a] = xl.y;
        }
    }
}

__device__ __forceinline__ unsigned long long dup2(float f) {
    unsigned long long r;
    asm("mov.b64 %0, {%1, %1};" : "=l"(r) : "r"(__float_as_uint(f)));
    return r;
}

// Skewed smem indexing — places the 4 rr chunks and 8 xb chunks a warp
// touches per LDS on pairwise-distinct bank groups (mod-128B all distinct).
__device__ __forceinline__ int rski(int a) { return a + ((a >> 4) << 2); }  // u64 units
__device__ __forceinline__ int xski(int b) { return b + ((b >> 5) << 2); }  // f32 units
constexpr int SRROW = 76;   // u64 per (s,il) row: 64 + 3*4 skew pads
constexpr int SXROW = 68;   // f32 per (s,il) row: 64 + 1*4 skew pad

// K4: jac[n][i][a][b] = sum_s g_R[s][i][a] * g_X[s][n][b].
// Block covers (2 n) x (2 i) x 64a x 64b; thread does an 8x8 tile with
// fma.rn.f32x2. R staged pre-duplicated (b64) in bank-conflict-free skewed
// smem; X skewed likewise and double-buffered across the s loop.
__global__ void __launch_bounds__(256, 2) k4_jac(float* __restrict__ jac) {
    __shared__ __align__(16) unsigned long long sR2[NSTEPS * 2 * SRROW]; // 19 KB
    __shared__ __align__(16) float sX[NSTEPS * 2 * SXROW];               // 8.5 KB
    const int tid = threadIdx.x, bid = blockIdx.x;
    const int n0 = (bid >> 5) << 1;   // 0,2,..,126
    const int i0 = (bid & 31) << 1;   // 0,2,..,62

    // Fill: 512 16B-chunks each of X and R (R duplicated into b64 halves).
#pragma unroll
    for (int v = tid; v < 512; v += 256) {
        const int s  = v >> 5;
        const int il = (v >> 4) & 1;
        const int aa = (v & 15) << 2;           // 0,4,..,60 (multiple of 4)
        float4 x = *(const float4*)&g_X[s][(n0 + il) * D + aa];
        float4 r = *(const float4*)&g_R[s][(i0 + il) * D + aa];
        *(float4*)&sX[(s * 2 + il) * SXROW + xski(aa)] = x;
        unsigned long long* rp = &sR2[(s * 2 + il) * SRROW + rski(aa)];
        *(ulonglong2*)rp       = make_ulonglong2(dup2(r.x), dup2(r.y));
        *(ulonglong2*)(rp + 2) = make_ulonglong2(dup2(r.z), dup2(r.w));
    }
    __syncthreads();

    const int nl  = (tid >> 7) & 1;
    const int il  = (tid >> 6) & 1;
    const int idx = tid & 63;
    const int a0  = (idx >> 3) << 3;
    const int b0  = (idx & 7) << 3;

    const unsigned long long* __restrict__ rbase = &sR2[il * SRROW + rski(a0)];
    const float* __restrict__ xbase              = &sX[nl * SXROW + xski(b0)];

    unsigned long long acc[8][4];
#pragma unroll
    for (int ia = 0; ia < 8; ia++)
#pragma unroll
        for (int jb = 0; jb < 4; jb++) acc[ia][jb] = 0ull;

    // Double-buffered xb; rr loaded at iteration top (ptxas hoists into the
    // previous FMA block with the remaining register headroom).
    unsigned long long xbA[4], xbB[4];
    {
        const ulonglong2 x01 = *(const ulonglong2*)&xbase[0];
        const ulonglong2 x23 = *(const ulonglong2*)&xbase[4];
        xbA[0] = x01.x; xbA[1] = x01.y; xbA[2] = x23.x; xbA[3] = x23.y;
    }

#pragma unroll
    for (int s = 0; s < NSTEPS; s++) {
        const unsigned long long* rp = rbase + (size_t)(s * 2) * SRROW;
        const ulonglong2 r01 = *(const ulonglong2*)(rp);
        const ulonglong2 r23 = *(const ulonglong2*)(rp + 2);
        const ulonglong2 r45 = *(const ulonglong2*)(rp + 4);
        const ulonglong2 r67 = *(const ulonglong2*)(rp + 6);
        const unsigned long long rr[8] = {r01.x, r01.y, r23.x, r23.y,
                                          r45.x, r45.y, r67.x, r67.y};
        if (s < NSTEPS - 1) {
            const float* xp = xbase + (size_t)((s + 1) * 2) * SXROW;
            const ulonglong2 x01 = *(const ulonglong2*)&xp[0];
            const ulonglong2 x23 = *(const ulonglong2*)&xp[4];
            unsigned long long* nxt = (s & 1) ? xbA : xbB;
            nxt[0] = x01.x; nxt[1] = x01.y; nxt[2] = x23.x; nxt[3] = x23.y;
        }
        const unsigned long long* xb = (s & 1) ? xbB : xbA;
#pragma unroll
        for (int ia = 0; ia < 8; ia++)
#pragma unroll
            for (int jb = 0; jb < 4; jb++)
                asm("fma.rn.f32x2 %0, %1, %2, %0;"
                    : "+l"(acc[ia][jb]) : "l"(rr[ia]), "l"(xb[jb]));
    }

    const size_t base = (((size_t)(n0 + nl) * D + (i0 + il)) * D) * D;
#pragma unroll
    for (int ia = 0; ia < 8; ia++) {
        float* p = jac + base + (size_t)(a0 + ia) * D + b0;
        *(ulonglong2*)p       = make_ulonglong2(acc[ia][0], acc[ia][1]);
        *(ulonglong2*)(p + 4) = make_ulonglong2(acc[ia][2], acc[ia][3]);
    }
}

extern "C" void kernel_launch(void* const* d_in, const int* in_sizes, int n_in,
                              void* d_out, int out_size) {
    const float* x0 = (const float*)d_in[0];
    const float* v0 = (const float*)d_in[1];
    const float* W  = (const float*)d_in[2];
    float* out = (float*)d_out;
    // output = [traj (frames x N x D)] then [jac (N x D x D x D)]
    float* jac = out + ((size_t)out_size - (size_t)N * D * D * D);

    kprep<<<48, 128>>>(x0, v0, W, out);
    k4_jac<<<2048, 256>>>(jac);
}

// round 9
// speedup vs baseline: 1.0682x; 1.0682x over previous
#include <cuda_runtime.h>
#include <cstddef>

// Problem constants (fixed by setup_inputs)
constexpr int D      = 64;
constexpr int N      = 128;
constexpr int NSTEPS = 16;

// ---------------- device scratch (no allocations allowed) ----------------
__device__ __align__(16) float g_R[NSTEPS][D * D];  // [s][i*64+a] = R_{15-s}[a][i]
__device__ __align__(16) float g_X[NSTEPS][N * D];  // x_s, s = 0..15

// KPREP: direct row-wise simulation of BOTH systems in one launch.
//   rows 0..127   : state rows (x0, v0)            -> g_X[t], traj frames
//   rows 128..191 : propagator rows a = row-128,
//                   X0 = dt^2*e_a, V0 = dt*e_a     -> X_k = R_k, stored transposed
__global__ void __launch_bounds__(128) kprep(const float* __restrict__ x0,
                                             const float* __restrict__ v0,
                                             const float* __restrict__ W,
                                             float* __restrict__ out) {
    __shared__ float sX[4][D];
    const int tid = threadIdx.x;
    const int w   = tid >> 5;                  // warp = local row
    const int l   = tid & 31;
    const int row = blockIdx.x * 4 + w;        // 0..191
    const int c0  = 2 * l;
    const float dt = 0.01f;
    const bool is_state = (row < N);
    const int a = row - N;                     // propagator row index (if !is_state)

    // Load this lane's two M columns into registers (fully unrolled).
    float mA[D], mB[D];
    {
        const float4* wa = (const float4*)(W + (size_t)c0 * D);
        const float4* wb = (const float4*)(W + (size_t)(c0 + 1) * D);
#pragma unroll
        for (int q = 0; q < 16; q++) {
            float4 va = wa[q], vb = wb[q];
            const int k = 4 * q;
            mA[k+0] = va.x - ((k+0) == c0     ? 1.0f : 0.0f);
            mA[k+1] = va.y - ((k+1) == c0     ? 1.0f : 0.0f);
            mA[k+2] = va.z - ((k+2) == c0     ? 1.0f : 0.0f);
            mA[k+3] = va.w - ((k+3) == c0     ? 1.0f : 0.0f);
            mB[k+0] = vb.x - ((k+0) == c0 + 1 ? 1.0f : 0.0f);
            mB[k+1] = vb.y - ((k+1) == c0 + 1 ? 1.0f : 0.0f);
            mB[k+2] = vb.z - ((k+2) == c0 + 1 ? 1.0f : 0.0f);
            mB[k+3] = vb.w - ((k+3) == c0 + 1 ? 1.0f : 0.0f);
        }
    }

    float2 xl, vl;
    if (is_state) {
        xl = *(const float2*)(x0 + (size_t)row * D + c0);
        vl = *(const float2*)(v0 + (size_t)row * D + c0);
    } else {
        xl = make_float2(c0 == a ? dt * dt : 0.0f, (c0 + 1) == a ? dt * dt : 0.0f);
        vl = make_float2(c0 == a ? dt      : 0.0f, (c0 + 1) == a ? dt      : 0.0f);
    }

    if (is_state) {
        *(float2*)&g_X[0][row * D + c0] = xl;                 // x_0
        *(float2*)(out + (size_t)row * D + c0) = xl;          // traj frame 0
    } else {
        g_R[15][c0 * D + a]       = xl.x;                     // R_0 transposed
        g_R[15][(c0 + 1) * D + a] = xl.y;
    }

    *(float2*)&sX[w][c0] = xl;
    __syncwarp();

#pragma unroll 1
    for (int t = 1; t <= NSTEPS; t++) {
        float2 y0 = make_float2(0.0f, 0.0f);
        float2 y1 = make_float2(0.0f, 0.0f);
#pragma unroll
        for (int k = 0; k < D; k += 2) {
            float xk0 = sX[w][k], xk1 = sX[w][k + 1];
            y0.x += xk0 * mA[k];     y0.y += xk0 * mB[k];
            y1.x += xk1 * mA[k + 1]; y1.y += xk1 * mB[k + 1];
        }
        float2 y = make_float2(y0.x + y1.x, y0.y + y1.y);
        vl.x += dt * y.x;  vl.y += dt * y.y;
        xl.x += dt * vl.x; xl.y += dt * vl.y;
        __syncwarp();
        *(float2*)&sX[w][c0] = xl;
        __syncwarp();

        if (is_state) {
            if (t < NSTEPS)
                *(float2*)&g_X[t][row * D + c0] = xl;
            if ((t & 3) == 0) {
                float* o = out + (size_t)(t >> 2) * (N * D) + (size_t)row * D + c0;
                *(float2*)o = xl;
            }
        } else if (t < NSTEPS) {
            g_R[15 - t][c0 * D + a]       = xl.x;
            g_R[15 - t][(c0 + 1) * D + a] = xl.y;
        }
    }
}

__device__ __forceinline__ unsigned long long dup2(float f) {
    unsigned long long r;
    asm("mov.b64 %0, {%1, %1};" : "=l"(r) : "r"(__float_as_uint(f)));
    return r;
}

// Cheap skew for sX only: per-8-float groups stay contiguous, and the 8 group
// starts a warp touches per LDS.128 land on distinct 16B banks mod 128B.
__device__ __forceinline__ int xski(int b) { return b + ((b >> 5) << 2); }  // f32 units
constexpr int SXROW = 68;   // f32 per (s,nl) row: 64 + 4 skew pad

// K4: jac[n][i][a][b] = sum_s g_R[s][i][a] * g_X[s][n][b].
// 512-thread block covers (2n x 2i x 64a x 64b); thread tile 4a x 8b with
// fma.rn.f32x2 (acc = 16 u64 = 32 regs). Small tile -> ~60 regs -> 2 CTAs of
// 512 per SM = 8 warps/SMSP: doubles latency hiding at constant FMA work.
// R staged pre-duplicated (b64), broadcast-read; X skew-padded; no double
// buffering (straight unrolled loop schedules best — R7 evidence).
__global__ void __launch_bounds__(512, 2) k4_jac(float* __restrict__ jac) {
    __shared__ __align__(16) unsigned long long sR2[NSTEPS][2][D];  // 16 KB
    __shared__ __align__(16) float sX[NSTEPS * 2 * SXROW];          // 8.5 KB
    const int tid = threadIdx.x, bid = blockIdx.x;
    const int n0 = (bid >> 5) << 1;   // 0,2,..,126
    const int i0 = (bid & 31) << 1;   // 0,2,..,62

    // Fill: one float4 of X and one float4 of R (dup'd to b64) per thread.
    {
        const int s  = tid >> 5;
        const int il = (tid >> 4) & 1;
        const int aa = (tid & 15) << 2;          // 0,4,..,60
        float4 x = *(const float4*)&g_X[s][(n0 + il) * D + aa];
        float4 r = *(const float4*)&g_R[s][(i0 + il) * D + aa];
        *(float4*)&sX[(s * 2 + il) * SXROW + xski(aa)] = x;
        unsigned long long* rp = &sR2[s][il][aa];
        *(ulonglong2*)rp       = make_ulonglong2(dup2(r.x), dup2(r.y));
        *(ulonglong2*)(rp + 2) = make_ulonglong2(dup2(r.z), dup2(r.w));
    }
    __syncthreads();

    const int nl  = (tid >> 8) & 1;
    const int il  = (tid >> 7) & 1;
    const int a0  = ((tid >> 3) & 15) << 2;   // 0,4,..,60
    const int b0  = (tid & 7) << 3;           // 0,8,..,56

    const unsigned long long* __restrict__ rbase = &sR2[0][il][a0];
    const float* __restrict__ xbase              = &sX[nl * SXROW + xski(b0)];

    unsigned long long acc[4][4];
#pragma unroll
    for (int ia = 0; ia < 4; ia++)
#pragma unroll
        for (int jb = 0; jb < 4; jb++) acc[ia][jb] = 0ull;

#pragma unroll
    for (int s = 0; s < NSTEPS; s++) {
        // rr: 4 pre-duplicated b64 (2 LDS.128, warp-broadcast: 4 distinct/line)
        const unsigned long long* rp = rbase + (size_t)s * (2 * D);
        const ulonglong2 r01 = *(const ulonglong2*)(rp);
        const ulonglong2 r23 = *(const ulonglong2*)(rp + 2);
        const unsigned long long rr[4] = {r01.x, r01.y, r23.x, r23.y};
        // xb: 8 floats = 4 packed f32x2 (2 LDS.128, conflict-free via skew)
        const float* xp = xbase + (size_t)s * (2 * SXROW);
        const ulonglong2 x01 = *(const ulonglong2*)&xp[0];
        const ulonglong2 x23 = *(const ulonglong2*)&xp[4];
        const unsigned long long xb[4] = {x01.x, x01.y, x23.x, x23.y};
#pragma unroll
        for (int ia = 0; ia < 4; ia++)
#pragma unroll
            for (int jb = 0; jb < 4; jb++)
                asm("fma.rn.f32x2 %0, %1, %2, %0;"
                    : "+l"(acc[ia][jb]) : "l"(rr[ia]), "l"(xb[jb]));
    }

    const size_t base = (((size_t)(n0 + nl) * D + (i0 + il)) * D) * D;
#pragma unroll
    for (int ia = 0; ia < 4; ia++) {
        float* p = jac + base + (size_t)(a0 + ia) * D + b0;
        *(ulonglong2*)p       = make_ulonglong2(acc[ia][0], acc[ia][1]);
        *(ulonglong2*)(p + 4) = make_ulonglong2(acc[ia][2], acc[ia][3]);
    }
}

extern "C" void kernel_launch(void* const* d_in, const int* in_sizes, int n_in,
                              void* d_out, int out_size) {
    const float* x0 = (const float*)d_in[0];
    const float* v0 = (const float*)d_in[1];
    const float* W  = (const float*)d_in[2];
    float* out = (float*)d_out;
    // output = [traj (frames x N x D)] then [jac (N x D x D x D)]
    float* jac = out + ((size_t)out_size - (size_t)N * D * D * D);

    kprep<<<48, 128>>>(x0, v0, W, out);
    k4_jac<<<2048, 512>>>(jac);
}